// round 7
// baseline (speedup 1.0000x reference)
#include <cuda_runtime.h>
#include <cuda_bf16.h>
#include <cstdint>
#include <math.h>

// Shapes: B=4,N=128,T=128 -> NTOK=65536 tokens, DIM=256, H=8, hd=32.
#define NTOK 65536
#define DIM  256
#define NCAT 768

// ---------------- device scratch (no allocations allowed) -------------------
__device__ __nv_bfloat16 g_a_hi[NTOK * DIM];
__device__ __nv_bfloat16 g_a_lo[NTOK * DIM];
__device__ __nv_bfloat16 g_w_hi[NCAT * DIM];     // [n][k] transposed cat(Wq,Wk,Wv)
__device__ __nv_bfloat16 g_w_lo[NCAT * DIM];
__device__ __nv_bfloat16 g_wp_hi[DIM * DIM];     // [n][k] transposed Wp
__device__ __nv_bfloat16 g_wp_lo[DIM * DIM];
__device__ float         g_c[(size_t)NTOK * NCAT];      // q|k|v per token (fp32)
__device__ __nv_bfloat16 g_x_hi[NTOK * DIM];
__device__ __nv_bfloat16 g_x_lo[NTOK * DIM];

// ---------------- helpers ---------------------------------------------------
__device__ __forceinline__ void ldsm4(unsigned* r, unsigned addr) {
    asm volatile("ldmatrix.sync.aligned.m8n8.x4.shared.b16 {%0,%1,%2,%3}, [%4];"
                 : "=r"(r[0]), "=r"(r[1]), "=r"(r[2]), "=r"(r[3]) : "r"(addr));
}
__device__ __forceinline__ void mma4(float* c, const unsigned* a, unsigned b0, unsigned b1) {
    asm volatile(
        "mma.sync.aligned.m16n8k16.row.col.f32.bf16.bf16.f32 "
        "{%0,%1,%2,%3}, {%4,%5,%6,%7}, {%8,%9}, {%0,%1,%2,%3};\n"
        : "+f"(c[0]), "+f"(c[1]), "+f"(c[2]), "+f"(c[3])
        : "r"(a[0]), "r"(a[1]), "r"(a[2]), "r"(a[3]), "r"(b0), "r"(b1));
}
__device__ __forceinline__ uint32_t smem_u32(const void* p) {
    uint32_t a;
    asm("{ .reg .u64 t; cvta.to.shared.u64 t, %1; cvt.u32.u64 %0, t; }" : "=r"(a) : "l"(p));
    return a;
}
#define CP_ASYNC16(dst, src) \
    asm volatile("cp.async.cg.shared.global [%0], [%1], 16;" :: "r"(dst), "l"(src))
#define CP_COMMIT() asm volatile("cp.async.commit_group;" ::: "memory")
#define CP_WAIT1()  asm volatile("cp.async.wait_group 1;" ::: "memory")
#define CP_WAIT0()  asm volatile("cp.async.wait_group 0;" ::: "memory")

// ---------------- merged pre-pass -------------------------------------------
// blocks [0, 16384): input split (one float4 per thread)
// blocks [16384, 16384+256): weight transpose+split; 64 blocks per weight.
#define SPLIT_BLOCKS 16384

__global__ __launch_bounds__(256)
void prepass_kernel(const float* __restrict__ v,
                    const float* __restrict__ Wq,
                    const float* __restrict__ Wk,
                    const float* __restrict__ Wv,
                    const float* __restrict__ Wp)
{
    __shared__ float tile[32][33];
    const int b   = blockIdx.x;
    const int tid = threadIdx.x;

    if (b < SPLIT_BLOCKS) {
        const int i = b * 256 + tid;
        const float4 x = reinterpret_cast<const float4*>(v)[i];
        __nv_bfloat162 h0 = __floats2bfloat162_rn(x.x, x.y);
        __nv_bfloat162 h1 = __floats2bfloat162_rn(x.z, x.w);
        __nv_bfloat162 l0 = __floats2bfloat162_rn(x.x - __bfloat162float(h0.x),
                                                  x.y - __bfloat162float(h0.y));
        __nv_bfloat162 l1 = __floats2bfloat162_rn(x.z - __bfloat162float(h1.x),
                                                  x.w - __bfloat162float(h1.y));
        reinterpret_cast<__nv_bfloat162*>(g_a_hi)[i * 2 + 0] = h0;
        reinterpret_cast<__nv_bfloat162*>(g_a_hi)[i * 2 + 1] = h1;
        reinterpret_cast<__nv_bfloat162*>(g_a_lo)[i * 2 + 0] = l0;
        reinterpret_cast<__nv_bfloat162*>(g_a_lo)[i * 2 + 1] = l1;
        return;
    }

    const int wb    = b - SPLIT_BLOCKS;   // 0..255
    const int which = wb >> 6;            // 0..3
    const int t     = wb & 63;
    const int bx = t & 7, by = t >> 3;
    const int tx = tid & 31, ty = tid >> 5;   // 32 x 8

    const float* W = (which == 0) ? Wq : (which == 1) ? Wk : (which == 2) ? Wv : Wp;
#pragma unroll
    for (int j = 0; j < 32; j += 8)
        tile[ty + j][tx] = W[(by * 32 + ty + j) * DIM + bx * 32 + tx];
    __syncthreads();
    __nv_bfloat16* ohi = (which < 3) ? (g_w_hi + which * DIM * DIM) : g_wp_hi;
    __nv_bfloat16* olo = (which < 3) ? (g_w_lo + which * DIM * DIM) : g_wp_lo;
#pragma unroll
    for (int j = 0; j < 32; j += 8) {
        const float val = tile[tx][ty + j];
        const int n = bx * 32 + ty + j;
        const int k = by * 32 + tx;
        const __nv_bfloat16 hb = __float2bfloat16_rn(val);
        ohi[n * DIM + k] = hb;
        olo[n * DIM + k] = __float2bfloat16_rn(val - __bfloat162float(hb));
    }
}

// ---------------- HMMA GEMM, 3-stage cp.async pipeline ----------------------
// Block tile 128(M) x 128(N), 512 threads = 16 warps as 4M x 4N, warp 32x32.
// K in 8 chunks of 32, triple-buffered, one __syncthreads per chunk.
// 3-pass bf16 split: ah*bh + ah*bl + al*bh.
#define ROWP   80
#define PLANE  (128 * ROWP)          // 10240
#define STAGE  (4 * PLANE)           // 40960
#define SMEM_GEMM (3 * STAGE)        // 122880

template<int ONC, bool IS_PROJ>
__global__ __launch_bounds__(512, 1)
void gemm_kernel(const __nv_bfloat16* __restrict__ Ahi,
                 const __nv_bfloat16* __restrict__ Alo,
                 const __nv_bfloat16* __restrict__ Bhi,
                 const __nv_bfloat16* __restrict__ Blo,
                 const float* __restrict__ bias,
                 float* __restrict__ outF)
{
    extern __shared__ __align__(128) char smem[];
    const uint32_t sbase = smem_u32(smem);

    const int tid  = threadIdx.x;
    const int warp = tid >> 5;
    const int lane = tid & 31;
    const int lane15 = lane & 15;
    const int laneHi = lane >> 4;
    const int gr = lane >> 2;
    const int qc = lane & 3;
    const int warpM = (warp >> 2) * 32;
    const int warpN = (warp & 3) * 32;
    const int colBase = blockIdx.x * 128;   // N fastest -> A-tile L2 reuse
    const int rowBase = blockIdx.y * 128;

    const int srow = tid >> 2;
    const int sseg = tid & 3;
    const uint32_t soff = srow * ROWP + sseg * 16;
    const size_t gaOff = (size_t)(rowBase + srow) * DIM + sseg * 8;
    const size_t gbOff = (size_t)(colBase + srow) * DIM + sseg * 8;

    auto issue_stage = [&](int c) {
        const uint32_t sb = sbase + (c % 3) * STAGE + soff;
        const int k0 = c * 32;
        CP_ASYNC16(sb            , Ahi + gaOff + k0);
        CP_ASYNC16(sb + PLANE    , Alo + gaOff + k0);
        CP_ASYNC16(sb + 2 * PLANE, Bhi + gbOff + k0);
        CP_ASYNC16(sb + 3 * PLANE, Blo + gbOff + k0);
        CP_COMMIT();
    };

    float acc[2][4][4];
#pragma unroll
    for (int mt = 0; mt < 2; mt++)
#pragma unroll
        for (int nt = 0; nt < 4; nt++)
#pragma unroll
            for (int i = 0; i < 4; i++) acc[mt][nt][i] = 0.f;

    const uint32_t aBase0 = sbase + (warpM + lane15) * ROWP + laneHi * 16;
    const uint32_t bBase0 = sbase + 2 * PLANE + (warpN + lane15) * ROWP + laneHi * 16;

    issue_stage(0);
    issue_stage(1);

#pragma unroll
    for (int c = 0; c < 8; c++) {
        if (c == 7) { CP_WAIT0(); } else { CP_WAIT1(); }
        __syncthreads();
        if (c + 2 < 8) issue_stage(c + 2);   // buffer (c-1)%3 is free after the sync

        const uint32_t aB = aBase0 + (c % 3) * STAGE;
        const uint32_t bB = bBase0 + (c % 3) * STAGE;
#pragma unroll
        for (int ks = 0; ks < 2; ks++) {
            unsigned ah[2][4], al[2][4], bh[2][4], bl[2][4];
#pragma unroll
            for (int mt = 0; mt < 2; mt++) {
                ldsm4(ah[mt], aB + mt * (16 * ROWP) + ks * 32);
                ldsm4(al[mt], aB + mt * (16 * ROWP) + ks * 32 + PLANE);
            }
#pragma unroll
            for (int nb = 0; nb < 2; nb++) {
                ldsm4(bh[nb], bB + nb * (16 * ROWP) + ks * 32);
                ldsm4(bl[nb], bB + nb * (16 * ROWP) + ks * 32 + PLANE);
            }
#pragma unroll
            for (int mt = 0; mt < 2; mt++)
#pragma unroll
                for (int nb = 0; nb < 2; nb++) {
                    mma4(acc[mt][2 * nb + 0], ah[mt], bh[nb][0], bh[nb][2]);
                    mma4(acc[mt][2 * nb + 1], ah[mt], bh[nb][1], bh[nb][3]);
                    mma4(acc[mt][2 * nb + 0], ah[mt], bl[nb][0], bl[nb][2]);
                    mma4(acc[mt][2 * nb + 1], ah[mt], bl[nb][1], bl[nb][3]);
                    mma4(acc[mt][2 * nb + 0], al[mt], bh[nb][0], bh[nb][2]);
                    mma4(acc[mt][2 * nb + 1], al[mt], bh[nb][1], bh[nb][3]);
                }
        }
    }

    // ---- epilogue
#pragma unroll
    for (int mt = 0; mt < 2; mt++)
#pragma unroll
        for (int nb = 0; nb < 2; nb++)
#pragma unroll
            for (int j = 0; j < 2; j++) {
                const float* cc = acc[mt][2 * nb + j];
                const int r   = rowBase + warpM + mt * 16 + gr;
                const int col = colBase + warpN + nb * 16 + j * 8 + qc * 2;
                if (IS_PROJ) {
                    const float b0 = bias[col], b1 = bias[col + 1];
                    *reinterpret_cast<float2*>(&outF[(size_t)(r    ) * ONC + col]) =
                        make_float2(cc[0] + b0, cc[1] + b1);
                    *reinterpret_cast<float2*>(&outF[(size_t)(r + 8) * ONC + col]) =
                        make_float2(cc[2] + b0, cc[3] + b1);
                } else {
                    *reinterpret_cast<float2*>(&g_c[(size_t)(r    ) * ONC + col]) =
                        make_float2(cc[0], cc[1]);
                    *reinterpret_cast<float2*>(&g_c[(size_t)(r + 8) * ONC + col]) =
                        make_float2(cc[2], cc[3]);
                }
            }
}

// ---------------- per-token head-axis attention -----------------------------
__global__ __launch_bounds__(256)
void attn_kernel()
{
    const int warp = threadIdx.x >> 5;
    const int lane = threadIdx.x & 31;
    const int token = blockIdx.x * 8 + warp;
    const size_t cb = (size_t)token * NCAT;

    float qr[8], kr[8], vr[8];
#pragma unroll
    for (int hh = 0; hh < 8; hh++) {
        const int d = hh * 32 + lane;
        qr[hh] = g_c[cb +       d];
        kr[hh] = g_c[cb + 256 + d];
        vr[hh] = g_c[cb + 512 + d];
    }

    const float scale = 0.17677669529663687f;   // 32^-0.5

#pragma unroll
    for (int hh = 0; hh < 8; hh++) {
        float m = -3.0e38f, l = 0.f, acc = 0.f;
#pragma unroll
        for (int g = 0; g < 8; g++) {
            float s = qr[hh] * kr[g];
#pragma unroll
            for (int o = 16; o > 0; o >>= 1)
                s += __shfl_xor_sync(0xffffffffu, s, o);
            s *= scale;
            const float mn   = fmaxf(m, s);
            const float corr = __expf(m - mn);
            const float e    = __expf(s - mn);
            acc = acc * corr + e * vr[g];
            l   = l   * corr + e;
            m   = mn;
        }
        const float val = acc / l;
        const int d = hh * 32 + lane;
        const __nv_bfloat16 hb = __float2bfloat16_rn(val);
        g_x_hi[(size_t)token * DIM + d] = hb;
        g_x_lo[(size_t)token * DIM + d] = __float2bfloat16_rn(val - __bfloat162float(hb));
    }
}

// ---------------------------------------------------------------------------
extern "C" void kernel_launch(void* const* d_in, const int* in_sizes, int n_in,
                              void* d_out, int out_size)
{
    const float* v  = (const float*)d_in[0];
    const float* Wq = (const float*)d_in[1];
    const float* Wk = (const float*)d_in[2];
    const float* Wv = (const float*)d_in[3];
    const float* Wp = (const float*)d_in[4];
    const float* bp = (const float*)d_in[5];
    float* out = (float*)d_out;

    void *pAhi, *pAlo, *pWhi, *pWlo, *pPhi, *pPlo, *pXhi, *pXlo;
    cudaGetSymbolAddress(&pAhi, g_a_hi);
    cudaGetSymbolAddress(&pAlo, g_a_lo);
    cudaGetSymbolAddress(&pWhi, g_w_hi);
    cudaGetSymbolAddress(&pWlo, g_w_lo);
    cudaGetSymbolAddress(&pPhi, g_wp_hi);
    cudaGetSymbolAddress(&pPlo, g_wp_lo);
    cudaGetSymbolAddress(&pXhi, g_x_hi);
    cudaGetSymbolAddress(&pXlo, g_x_lo);

    cudaFuncSetAttribute(gemm_kernel<NCAT, false>,
                         cudaFuncAttributeMaxDynamicSharedMemorySize, SMEM_GEMM);
    cudaFuncSetAttribute(gemm_kernel<DIM, true>,
                         cudaFuncAttributeMaxDynamicSharedMemorySize, SMEM_GEMM);

    prepass_kernel<<<SPLIT_BLOCKS + 256, 256>>>(v, Wq, Wk, Wv, Wp);

    dim3 qkv_grid(NCAT / 128, NTOK / 128);   // (6, 512), N fastest
    gemm_kernel<NCAT, false><<<qkv_grid, 512, SMEM_GEMM>>>(
        (const __nv_bfloat16*)pAhi, (const __nv_bfloat16*)pAlo,
        (const __nv_bfloat16*)pWhi, (const __nv_bfloat16*)pWlo,
        nullptr, nullptr);

    attn_kernel<<<NTOK / 8, 256>>>();

    dim3 proj_grid(DIM / 128, NTOK / 128);   // (2, 512)
    gemm_kernel<DIM, true><<<proj_grid, 512, SMEM_GEMM>>>(
        (const __nv_bfloat16*)pXhi, (const __nv_bfloat16*)pXlo,
        (const __nv_bfloat16*)pPhi, (const __nv_bfloat16*)pPlo,
        bp, out);
}

// round 8
// speedup vs baseline: 1.6338x; 1.6338x over previous
#include <cuda_runtime.h>
#include <cuda_bf16.h>
#include <cstdint>
#include <math.h>

// Shapes: B=4,N=128,T=128 -> NTOK=65536 tokens, DIM=256, H=8, hd=32.
#define NTOK 65536
#define DIM  256
#define NCAT 768

// ---------------- device scratch (no allocations allowed) -------------------
__device__ __nv_bfloat16 g_a_hi[NTOK * DIM];
__device__ __nv_bfloat16 g_a_lo[NTOK * DIM];
__device__ __nv_bfloat16 g_w_hi[NCAT * DIM];     // [n][k] transposed cat(Wq,Wk,Wv)
__device__ __nv_bfloat16 g_w_lo[NCAT * DIM];
__device__ __nv_bfloat16 g_wp_hi[DIM * DIM];     // [n][k] transposed Wp
__device__ __nv_bfloat16 g_wp_lo[DIM * DIM];
__device__ float         g_c[(size_t)NTOK * NCAT];      // q|k|v per token (fp32)
__device__ __nv_bfloat16 g_x_hi[NTOK * DIM];
__device__ __nv_bfloat16 g_x_lo[NTOK * DIM];

// ---------------- helpers ---------------------------------------------------
__device__ __forceinline__ void ldsm4(unsigned* r, unsigned addr) {
    asm volatile("ldmatrix.sync.aligned.m8n8.x4.shared.b16 {%0,%1,%2,%3}, [%4];"
                 : "=r"(r[0]), "=r"(r[1]), "=r"(r[2]), "=r"(r[3]) : "r"(addr));
}
__device__ __forceinline__ void mma4(float* c, const unsigned* a, unsigned b0, unsigned b1) {
    asm volatile(
        "mma.sync.aligned.m16n8k16.row.col.f32.bf16.bf16.f32 "
        "{%0,%1,%2,%3}, {%4,%5,%6,%7}, {%8,%9}, {%0,%1,%2,%3};\n"
        : "+f"(c[0]), "+f"(c[1]), "+f"(c[2]), "+f"(c[3])
        : "r"(a[0]), "r"(a[1]), "r"(a[2]), "r"(a[3]), "r"(b0), "r"(b1));
}
__device__ __forceinline__ uint32_t smem_u32(const void* p) {
    uint32_t a;
    asm("{ .reg .u64 t; cvta.to.shared.u64 t, %1; cvt.u32.u64 %0, t; }" : "=r"(a) : "l"(p));
    return a;
}
#define CP_ASYNC16(dst, src) \
    asm volatile("cp.async.cg.shared.global [%0], [%1], 16;" :: "r"(dst), "l"(src))
#define CP_COMMIT() asm volatile("cp.async.commit_group;" ::: "memory")
#define CP_WAIT1()  asm volatile("cp.async.wait_group 1;" ::: "memory")
#define CP_WAIT0()  asm volatile("cp.async.wait_group 0;" ::: "memory")

// ---------------- merged pre-pass -------------------------------------------
// blocks [0, 16384): input split (one float4 per thread)
// blocks [16384, 16384+256): weight transpose+split; 64 blocks per weight.
#define SPLIT_BLOCKS 16384

__global__ __launch_bounds__(256)
void prepass_kernel(const float* __restrict__ v,
                    const float* __restrict__ Wq,
                    const float* __restrict__ Wk,
                    const float* __restrict__ Wv,
                    const float* __restrict__ Wp)
{
    __shared__ float tile[32][33];
    const int b   = blockIdx.x;
    const int tid = threadIdx.x;

    if (b < SPLIT_BLOCKS) {
        const int i = b * 256 + tid;
        const float4 x = reinterpret_cast<const float4*>(v)[i];
        __nv_bfloat162 h0 = __floats2bfloat162_rn(x.x, x.y);
        __nv_bfloat162 h1 = __floats2bfloat162_rn(x.z, x.w);
        __nv_bfloat162 l0 = __floats2bfloat162_rn(x.x - __bfloat162float(h0.x),
                                                  x.y - __bfloat162float(h0.y));
        __nv_bfloat162 l1 = __floats2bfloat162_rn(x.z - __bfloat162float(h1.x),
                                                  x.w - __bfloat162float(h1.y));
        reinterpret_cast<__nv_bfloat162*>(g_a_hi)[i * 2 + 0] = h0;
        reinterpret_cast<__nv_bfloat162*>(g_a_hi)[i * 2 + 1] = h1;
        reinterpret_cast<__nv_bfloat162*>(g_a_lo)[i * 2 + 0] = l0;
        reinterpret_cast<__nv_bfloat162*>(g_a_lo)[i * 2 + 1] = l1;
        return;
    }

    const int wb    = b - SPLIT_BLOCKS;   // 0..255
    const int which = wb >> 6;            // 0..3
    const int t     = wb & 63;
    const int bx = t & 7, by = t >> 3;
    const int tx = tid & 31, ty = tid >> 5;   // 32 x 8

    const float* W = (which == 0) ? Wq : (which == 1) ? Wk : (which == 2) ? Wv : Wp;
#pragma unroll
    for (int j = 0; j < 32; j += 8)
        tile[ty + j][tx] = W[(by * 32 + ty + j) * DIM + bx * 32 + tx];
    __syncthreads();
    __nv_bfloat16* ohi = (which < 3) ? (g_w_hi + which * DIM * DIM) : g_wp_hi;
    __nv_bfloat16* olo = (which < 3) ? (g_w_lo + which * DIM * DIM) : g_wp_lo;
#pragma unroll
    for (int j = 0; j < 32; j += 8) {
        const float val = tile[tx][ty + j];
        const int n = bx * 32 + ty + j;
        const int k = by * 32 + tx;
        const __nv_bfloat16 hb = __float2bfloat16_rn(val);
        ohi[n * DIM + k] = hb;
        olo[n * DIM + k] = __float2bfloat16_rn(val - __bfloat162float(hb));
    }
}

// ---------------- HMMA GEMM, 2-stage cp.async pipeline, 2 CTAs/SM -----------
// Block tile 128(M) x 128(N), 512 threads = 16 warps as 4M x 4N, warp 32x32.
// K in 8 chunks of 32, double-buffered via cp.async (2-deep pipeline).
// 3-pass bf16 split: ah*bh + ah*bl + al*bh.
#define ROWP   80
#define PLANE  (128 * ROWP)          // 10240
#define STAGE  (4 * PLANE)           // 40960
#define SMEM_GEMM (2 * STAGE)        // 81920

template<int ONC, bool IS_PROJ>
__global__ __launch_bounds__(512, 2)
void gemm_kernel(const __nv_bfloat16* __restrict__ Ahi,
                 const __nv_bfloat16* __restrict__ Alo,
                 const __nv_bfloat16* __restrict__ Bhi,
                 const __nv_bfloat16* __restrict__ Blo,
                 const float* __restrict__ bias,
                 float* __restrict__ outF)
{
    extern __shared__ __align__(128) char smem[];
    const uint32_t sbase = smem_u32(smem);

    const int tid  = threadIdx.x;
    const int warp = tid >> 5;
    const int lane = tid & 31;
    const int lane15 = lane & 15;
    const int laneHi = lane >> 4;
    const int gr = lane >> 2;
    const int qc = lane & 3;
    const int warpM = (warp >> 2) * 32;
    const int warpN = (warp & 3) * 32;
    const int colBase = blockIdx.x * 128;   // N fastest -> A-tile L2 reuse
    const int rowBase = blockIdx.y * 128;

    const int srow = tid >> 2;
    const int sseg = tid & 3;
    const uint32_t soff = srow * ROWP + sseg * 16;
    const size_t gaOff = (size_t)(rowBase + srow) * DIM + sseg * 8;
    const size_t gbOff = (size_t)(colBase + srow) * DIM + sseg * 8;

    auto issue_stage = [&](int c, int buf) {
        const uint32_t sb = sbase + buf * STAGE + soff;
        const int k0 = c * 32;
        CP_ASYNC16(sb            , Ahi + gaOff + k0);
        CP_ASYNC16(sb + PLANE    , Alo + gaOff + k0);
        CP_ASYNC16(sb + 2 * PLANE, Bhi + gbOff + k0);
        CP_ASYNC16(sb + 3 * PLANE, Blo + gbOff + k0);
        CP_COMMIT();
    };

    float acc[2][4][4];
#pragma unroll
    for (int mt = 0; mt < 2; mt++)
#pragma unroll
        for (int nt = 0; nt < 4; nt++)
#pragma unroll
            for (int i = 0; i < 4; i++) acc[mt][nt][i] = 0.f;

    const uint32_t aBase0 = sbase + (warpM + lane15) * ROWP + laneHi * 16;
    const uint32_t bBase0 = sbase + 2 * PLANE + (warpN + lane15) * ROWP + laneHi * 16;

    issue_stage(0, 0);
    issue_stage(1, 1);

#pragma unroll
    for (int c = 0; c < 8; c++) {
        const int buf = c & 1;
        // Group for chunk c must be fully landed: with 2-deep issue, wait1
        // suffices except at the last chunk where chunk 7's own group is the
        // newest pending one.
        if (c == 7) { CP_WAIT0(); } else { CP_WAIT1(); }
        __syncthreads();

        const uint32_t aB = aBase0 + buf * STAGE;
        const uint32_t bB = bBase0 + buf * STAGE;
#pragma unroll
        for (int ks = 0; ks < 2; ks++) {
            unsigned ah[2][4], al[2][4], bh[2][4], bl[2][4];
#pragma unroll
            for (int mt = 0; mt < 2; mt++) {
                ldsm4(ah[mt], aB + mt * (16 * ROWP) + ks * 32);
                ldsm4(al[mt], aB + mt * (16 * ROWP) + ks * 32 + PLANE);
            }
#pragma unroll
            for (int nb = 0; nb < 2; nb++) {
                ldsm4(bh[nb], bB + nb * (16 * ROWP) + ks * 32);
                ldsm4(bl[nb], bB + nb * (16 * ROWP) + ks * 32 + PLANE);
            }
#pragma unroll
            for (int mt = 0; mt < 2; mt++)
#pragma unroll
                for (int nb = 0; nb < 2; nb++) {
                    mma4(acc[mt][2 * nb + 0], ah[mt], bh[nb][0], bh[nb][2]);
                    mma4(acc[mt][2 * nb + 1], ah[mt], bh[nb][1], bh[nb][3]);
                    mma4(acc[mt][2 * nb + 0], ah[mt], bl[nb][0], bl[nb][2]);
                    mma4(acc[mt][2 * nb + 1], ah[mt], bl[nb][1], bl[nb][3]);
                    mma4(acc[mt][2 * nb + 0], al[mt], bh[nb][0], bh[nb][2]);
                    mma4(acc[mt][2 * nb + 1], al[mt], bh[nb][1], bh[nb][3]);
                }
        }
        __syncthreads();
        if (c + 2 < 8) issue_stage(c + 2, buf);
    }

    // ---- epilogue
#pragma unroll
    for (int mt = 0; mt < 2; mt++)
#pragma unroll
        for (int nb = 0; nb < 2; nb++)
#pragma unroll
            for (int j = 0; j < 2; j++) {
                const float* cc = acc[mt][2 * nb + j];
                const int r   = rowBase + warpM + mt * 16 + gr;
                const int col = colBase + warpN + nb * 16 + j * 8 + qc * 2;
                if (IS_PROJ) {
                    const float b0 = bias[col], b1 = bias[col + 1];
                    *reinterpret_cast<float2*>(&outF[(size_t)(r    ) * ONC + col]) =
                        make_float2(cc[0] + b0, cc[1] + b1);
                    *reinterpret_cast<float2*>(&outF[(size_t)(r + 8) * ONC + col]) =
                        make_float2(cc[2] + b0, cc[3] + b1);
                } else {
                    *reinterpret_cast<float2*>(&g_c[(size_t)(r    ) * ONC + col]) =
                        make_float2(cc[0], cc[1]);
                    *reinterpret_cast<float2*>(&g_c[(size_t)(r + 8) * ONC + col]) =
                        make_float2(cc[2], cc[3]);
                }
            }
}

// ---------------- per-token head-axis attention -----------------------------
__global__ __launch_bounds__(256)
void attn_kernel()
{
    const int warp = threadIdx.x >> 5;
    const int lane = threadIdx.x & 31;
    const int token = blockIdx.x * 8 + warp;
    const size_t cb = (size_t)token * NCAT;

    float qr[8], kr[8], vr[8];
#pragma unroll
    for (int hh = 0; hh < 8; hh++) {
        const int d = hh * 32 + lane;
        qr[hh] = g_c[cb +       d];
        kr[hh] = g_c[cb + 256 + d];
        vr[hh] = g_c[cb + 512 + d];
    }

    const float scale = 0.17677669529663687f;   // 32^-0.5

#pragma unroll
    for (int hh = 0; hh < 8; hh++) {
        float m = -3.0e38f, l = 0.f, acc = 0.f;
#pragma unroll
        for (int g = 0; g < 8; g++) {
            float s = qr[hh] * kr[g];
#pragma unroll
            for (int o = 16; o > 0; o >>= 1)
                s += __shfl_xor_sync(0xffffffffu, s, o);
            s *= scale;
            const float mn   = fmaxf(m, s);
            const float corr = __expf(m - mn);
            const float e    = __expf(s - mn);
            acc = acc * corr + e * vr[g];
            l   = l   * corr + e;
            m   = mn;
        }
        const float val = acc / l;
        const int d = hh * 32 + lane;
        const __nv_bfloat16 hb = __float2bfloat16_rn(val);
        g_x_hi[(size_t)token * DIM + d] = hb;
        g_x_lo[(size_t)token * DIM + d] = __float2bfloat16_rn(val - __bfloat162float(hb));
    }
}

// ---------------------------------------------------------------------------
extern "C" void kernel_launch(void* const* d_in, const int* in_sizes, int n_in,
                              void* d_out, int out_size)
{
    const float* v  = (const float*)d_in[0];
    const float* Wq = (const float*)d_in[1];
    const float* Wk = (const float*)d_in[2];
    const float* Wv = (const float*)d_in[3];
    const float* Wp = (const float*)d_in[4];
    const float* bp = (const float*)d_in[5];
    float* out = (float*)d_out;

    void *pAhi, *pAlo, *pWhi, *pWlo, *pPhi, *pPlo, *pXhi, *pXlo;
    cudaGetSymbolAddress(&pAhi, g_a_hi);
    cudaGetSymbolAddress(&pAlo, g_a_lo);
    cudaGetSymbolAddress(&pWhi, g_w_hi);
    cudaGetSymbolAddress(&pWlo, g_w_lo);
    cudaGetSymbolAddress(&pPhi, g_wp_hi);
    cudaGetSymbolAddress(&pPlo, g_wp_lo);
    cudaGetSymbolAddress(&pXhi, g_x_hi);
    cudaGetSymbolAddress(&pXlo, g_x_lo);

    cudaFuncSetAttribute(gemm_kernel<NCAT, false>,
                         cudaFuncAttributeMaxDynamicSharedMemorySize, SMEM_GEMM);
    cudaFuncSetAttribute(gemm_kernel<DIM, true>,
                         cudaFuncAttributeMaxDynamicSharedMemorySize, SMEM_GEMM);

    prepass_kernel<<<SPLIT_BLOCKS + 256, 256>>>(v, Wq, Wk, Wv, Wp);

    dim3 qkv_grid(NCAT / 128, NTOK / 128);   // (6, 512), N fastest
    gemm_kernel<NCAT, false><<<qkv_grid, 512, SMEM_GEMM>>>(
        (const __nv_bfloat16*)pAhi, (const __nv_bfloat16*)pAlo,
        (const __nv_bfloat16*)pWhi, (const __nv_bfloat16*)pWlo,
        nullptr, nullptr);

    attn_kernel<<<NTOK / 8, 256>>>();

    dim3 proj_grid(DIM / 128, NTOK / 128);   // (2, 512)
    gemm_kernel<DIM, true><<<proj_grid, 512, SMEM_GEMM>>>(
        (const __nv_bfloat16*)pXhi, (const __nv_bfloat16*)pXlo,
        (const __nv_bfloat16*)pPhi, (const __nv_bfloat16*)pPlo,
        bp, out);
}

// round 9
// speedup vs baseline: 1.9572x; 1.1979x over previous
#include <cuda_runtime.h>
#include <cuda_fp16.h>
#include <cstdint>
#include <math.h>

// Shapes: B=4,N=128,T=128 -> NTOK=65536 tokens, DIM=256, H=8, hd=32.
#define NTOK 65536
#define DIM  256
#define NCAT 768

// ---------------- device scratch (no allocations allowed) -------------------
__device__ __half g_a_hi[NTOK * DIM];
__device__ __half g_a_lo[NTOK * DIM];
__device__ __half g_w_h [NCAT * DIM];    // [n][k] transposed cat(Wq,Wk,Wv), fp16
__device__ __half g_wp_h[DIM * DIM];     // [n][k] transposed Wp, fp16
__device__ float  g_c[(size_t)NTOK * NCAT];     // q|k|v per token (fp32)
__device__ __half g_x_hi[NTOK * DIM];
__device__ __half g_x_lo[NTOK * DIM];

// ---------------- helpers ---------------------------------------------------
__device__ __forceinline__ void ldsm4(unsigned* r, unsigned addr) {
    asm volatile("ldmatrix.sync.aligned.m8n8.x4.shared.b16 {%0,%1,%2,%3}, [%4];"
                 : "=r"(r[0]), "=r"(r[1]), "=r"(r[2]), "=r"(r[3]) : "r"(addr));
}
__device__ __forceinline__ void mma4(float* c, const unsigned* a, unsigned b0, unsigned b1) {
    asm volatile(
        "mma.sync.aligned.m16n8k16.row.col.f32.f16.f16.f32 "
        "{%0,%1,%2,%3}, {%4,%5,%6,%7}, {%8,%9}, {%0,%1,%2,%3};\n"
        : "+f"(c[0]), "+f"(c[1]), "+f"(c[2]), "+f"(c[3])
        : "r"(a[0]), "r"(a[1]), "r"(a[2]), "r"(a[3]), "r"(b0), "r"(b1));
}
__device__ __forceinline__ uint32_t smem_u32(const void* p) {
    uint32_t a;
    asm("{ .reg .u64 t; cvta.to.shared.u64 t, %1; cvt.u32.u64 %0, t; }" : "=r"(a) : "l"(p));
    return a;
}
#define CP_ASYNC16(dst, src) \
    asm volatile("cp.async.cg.shared.global [%0], [%1], 16;" :: "r"(dst), "l"(src))
#define CP_COMMIT() asm volatile("cp.async.commit_group;" ::: "memory")
#define CP_WAIT1()  asm volatile("cp.async.wait_group 1;" ::: "memory")
#define CP_WAIT0()  asm volatile("cp.async.wait_group 0;" ::: "memory")

// ---------------- merged pre-pass -------------------------------------------
// blocks [0, 16384): input split into fp16 hi/lo (one float4 per thread)
// blocks [16384, 16384+256): weight transpose + fp16 convert (hi only).
#define SPLIT_BLOCKS 16384

__global__ __launch_bounds__(256)
void prepass_kernel(const float* __restrict__ v,
                    const float* __restrict__ Wq,
                    const float* __restrict__ Wk,
                    const float* __restrict__ Wv,
                    const float* __restrict__ Wp)
{
    __shared__ float tile[32][33];
    const int b   = blockIdx.x;
    const int tid = threadIdx.x;

    if (b < SPLIT_BLOCKS) {
        const int i = b * 256 + tid;
        const float4 x = reinterpret_cast<const float4*>(v)[i];
        __half2 h0 = __floats2half2_rn(x.x, x.y);
        __half2 h1 = __floats2half2_rn(x.z, x.w);
        __half2 l0 = __floats2half2_rn(x.x - __half2float(__low2half(h0)),
                                       x.y - __half2float(__high2half(h0)));
        __half2 l1 = __floats2half2_rn(x.z - __half2float(__low2half(h1)),
                                       x.w - __half2float(__high2half(h1)));
        reinterpret_cast<__half2*>(g_a_hi)[i * 2 + 0] = h0;
        reinterpret_cast<__half2*>(g_a_hi)[i * 2 + 1] = h1;
        reinterpret_cast<__half2*>(g_a_lo)[i * 2 + 0] = l0;
        reinterpret_cast<__half2*>(g_a_lo)[i * 2 + 1] = l1;
        return;
    }

    const int wb    = b - SPLIT_BLOCKS;   // 0..255
    const int which = wb >> 6;            // 0..3
    const int t     = wb & 63;
    const int bx = t & 7, by = t >> 3;
    const int tx = tid & 31, ty = tid >> 5;   // 32 x 8

    const float* W = (which == 0) ? Wq : (which == 1) ? Wk : (which == 2) ? Wv : Wp;
#pragma unroll
    for (int j = 0; j < 32; j += 8)
        tile[ty + j][tx] = W[(by * 32 + ty + j) * DIM + bx * 32 + tx];
    __syncthreads();
    __half* oh = (which < 3) ? (g_w_h + which * DIM * DIM) : g_wp_h;
#pragma unroll
    for (int j = 0; j < 32; j += 8) {
        const float val = tile[tx][ty + j];
        const int n = bx * 32 + ty + j;
        const int k = by * 32 + tx;
        oh[n * DIM + k] = __float2half_rn(val);
    }
}

// ---------------- HMMA GEMM, 2-stage cp.async pipeline, 2 CTAs/SM -----------
// Block tile 128(M) x 128(N), 512 threads = 16 warps as 4M x 4N, warp 32x32.
// K in 8 chunks of 32, double-buffered via cp.async.
// 2-pass fp16 split (A split, B single-plane): D = Ah*Bh + Al*Bh.
#define ROWP   80
#define PLANE  (128 * ROWP)          // 10240
#define STAGE  (3 * PLANE)           // 30720 (Ahi, Alo, Bh)
#define SMEM_GEMM (2 * STAGE)        // 61440

template<int ONC, bool IS_PROJ>
__global__ __launch_bounds__(512, 2)
void gemm_kernel(const __half* __restrict__ Ahi,
                 const __half* __restrict__ Alo,
                 const __half* __restrict__ Bh,
                 const float* __restrict__ bias,
                 float* __restrict__ outF)
{
    extern __shared__ __align__(128) char smem[];
    const uint32_t sbase = smem_u32(smem);

    const int tid  = threadIdx.x;
    const int warp = tid >> 5;
    const int lane = tid & 31;
    const int lane15 = lane & 15;
    const int laneHi = lane >> 4;
    const int gr = lane >> 2;
    const int qc = lane & 3;
    const int warpM = (warp >> 2) * 32;
    const int warpN = (warp & 3) * 32;
    const int colBase = blockIdx.x * 128;   // N fastest -> A-tile L2 reuse
    const int rowBase = blockIdx.y * 128;

    const int srow = tid >> 2;
    const int sseg = tid & 3;
    const uint32_t soff = srow * ROWP + sseg * 16;
    const size_t gaOff = (size_t)(rowBase + srow) * DIM + sseg * 8;
    const size_t gbOff = (size_t)(colBase + srow) * DIM + sseg * 8;

    auto issue_stage = [&](int c, int buf) {
        const uint32_t sb = sbase + buf * STAGE + soff;
        const int k0 = c * 32;
        CP_ASYNC16(sb            , Ahi + gaOff + k0);
        CP_ASYNC16(sb + PLANE    , Alo + gaOff + k0);
        CP_ASYNC16(sb + 2 * PLANE, Bh  + gbOff + k0);
        CP_COMMIT();
    };

    float acc[2][4][4];
#pragma unroll
    for (int mt = 0; mt < 2; mt++)
#pragma unroll
        for (int nt = 0; nt < 4; nt++)
#pragma unroll
            for (int i = 0; i < 4; i++) acc[mt][nt][i] = 0.f;

    const uint32_t aBase0 = sbase + (warpM + lane15) * ROWP + laneHi * 16;
    const uint32_t bBase0 = sbase + 2 * PLANE + (warpN + lane15) * ROWP + laneHi * 16;

    issue_stage(0, 0);
    issue_stage(1, 1);

#pragma unroll
    for (int c = 0; c < 8; c++) {
        const int buf = c & 1;
        if (c == 7) { CP_WAIT0(); } else { CP_WAIT1(); }
        __syncthreads();

        const uint32_t aB = aBase0 + buf * STAGE;
        const uint32_t bB = bBase0 + buf * STAGE;
#pragma unroll
        for (int ks = 0; ks < 2; ks++) {
            unsigned ah[2][4], al[2][4], bh[2][4];
#pragma unroll
            for (int mt = 0; mt < 2; mt++) {
                ldsm4(ah[mt], aB + mt * (16 * ROWP) + ks * 32);
                ldsm4(al[mt], aB + mt * (16 * ROWP) + ks * 32 + PLANE);
            }
#pragma unroll
            for (int nb = 0; nb < 2; nb++)
                ldsm4(bh[nb], bB + nb * (16 * ROWP) + ks * 32);
#pragma unroll
            for (int mt = 0; mt < 2; mt++)
#pragma unroll
                for (int nb = 0; nb < 2; nb++) {
                    mma4(acc[mt][2 * nb + 0], ah[mt], bh[nb][0], bh[nb][2]);
                    mma4(acc[mt][2 * nb + 1], ah[mt], bh[nb][1], bh[nb][3]);
                    mma4(acc[mt][2 * nb + 0], al[mt], bh[nb][0], bh[nb][2]);
                    mma4(acc[mt][2 * nb + 1], al[mt], bh[nb][1], bh[nb][3]);
                }
        }
        __syncthreads();
        if (c + 2 < 8) issue_stage(c + 2, buf);
    }

    // ---- epilogue
#pragma unroll
    for (int mt = 0; mt < 2; mt++)
#pragma unroll
        for (int nb = 0; nb < 2; nb++)
#pragma unroll
            for (int j = 0; j < 2; j++) {
                const float* cc = acc[mt][2 * nb + j];
                const int r   = rowBase + warpM + mt * 16 + gr;
                const int col = colBase + warpN + nb * 16 + j * 8 + qc * 2;
                if (IS_PROJ) {
                    const float b0 = bias[col], b1 = bias[col + 1];
                    *reinterpret_cast<float2*>(&outF[(size_t)(r    ) * ONC + col]) =
                        make_float2(cc[0] + b0, cc[1] + b1);
                    *reinterpret_cast<float2*>(&outF[(size_t)(r + 8) * ONC + col]) =
                        make_float2(cc[2] + b0, cc[3] + b1);
                } else {
                    *reinterpret_cast<float2*>(&g_c[(size_t)(r    ) * ONC + col]) =
                        make_float2(cc[0], cc[1]);
                    *reinterpret_cast<float2*>(&g_c[(size_t)(r + 8) * ONC + col]) =
                        make_float2(cc[2], cc[3]);
                }
            }
}

// ---------------- per-token head-axis attention -----------------------------
__global__ __launch_bounds__(256)
void attn_kernel()
{
    const int warp = threadIdx.x >> 5;
    const int lane = threadIdx.x & 31;
    const int token = blockIdx.x * 8 + warp;
    const size_t cb = (size_t)token * NCAT;

    float qr[8], kr[8], vr[8];
#pragma unroll
    for (int hh = 0; hh < 8; hh++) {
        const int d = hh * 32 + lane;
        qr[hh] = g_c[cb +       d];
        kr[hh] = g_c[cb + 256 + d];
        vr[hh] = g_c[cb + 512 + d];
    }

    const float scale = 0.17677669529663687f;   // 32^-0.5

#pragma unroll
    for (int hh = 0; hh < 8; hh++) {
        float m = -3.0e38f, l = 0.f, acc = 0.f;
#pragma unroll
        for (int g = 0; g < 8; g++) {
            float s = qr[hh] * kr[g];
#pragma unroll
            for (int o = 16; o > 0; o >>= 1)
                s += __shfl_xor_sync(0xffffffffu, s, o);
            s *= scale;
            const float mn   = fmaxf(m, s);
            const float corr = __expf(m - mn);
            const float e    = __expf(s - mn);
            acc = acc * corr + e * vr[g];
            l   = l   * corr + e;
            m   = mn;
        }
        const float val = acc / l;
        const int d = hh * 32 + lane;
        const __half hb = __float2half_rn(val);
        g_x_hi[(size_t)token * DIM + d] = hb;
        g_x_lo[(size_t)token * DIM + d] = __float2half_rn(val - __half2float(hb));
    }
}

// ---------------------------------------------------------------------------
extern "C" void kernel_launch(void* const* d_in, const int* in_sizes, int n_in,
                              void* d_out, int out_size)
{
    const float* v  = (const float*)d_in[0];
    const float* Wq = (const float*)d_in[1];
    const float* Wk = (const float*)d_in[2];
    const float* Wv = (const float*)d_in[3];
    const float* Wp = (const float*)d_in[4];
    const float* bp = (const float*)d_in[5];
    float* out = (float*)d_out;

    void *pAhi, *pAlo, *pWh, *pPh, *pXhi, *pXlo;
    cudaGetSymbolAddress(&pAhi, g_a_hi);
    cudaGetSymbolAddress(&pAlo, g_a_lo);
    cudaGetSymbolAddress(&pWh,  g_w_h);
    cudaGetSymbolAddress(&pPh,  g_wp_h);
    cudaGetSymbolAddress(&pXhi, g_x_hi);
    cudaGetSymbolAddress(&pXlo, g_x_lo);

    cudaFuncSetAttribute(gemm_kernel<NCAT, false>,
                         cudaFuncAttributeMaxDynamicSharedMemorySize, SMEM_GEMM);
    cudaFuncSetAttribute(gemm_kernel<DIM, true>,
                         cudaFuncAttributeMaxDynamicSharedMemorySize, SMEM_GEMM);

    prepass_kernel<<<SPLIT_BLOCKS + 256, 256>>>(v, Wq, Wk, Wv, Wp);

    dim3 qkv_grid(NCAT / 128, NTOK / 128);   // (6, 512), N fastest
    gemm_kernel<NCAT, false><<<qkv_grid, 512, SMEM_GEMM>>>(
        (const __half*)pAhi, (const __half*)pAlo,
        (const __half*)pWh, nullptr, nullptr);

    attn_kernel<<<NTOK / 8, 256>>>();

    dim3 proj_grid(DIM / 128, NTOK / 128);   // (2, 512)
    gemm_kernel<DIM, true><<<proj_grid, 512, SMEM_GEMM>>>(
        (const __half*)pXhi, (const __half*)pXlo,
        (const __half*)pPh, bp, out);
}

// round 10
// speedup vs baseline: 2.0196x; 1.0319x over previous
#include <cuda_runtime.h>
#include <cuda_fp16.h>
#include <cstdint>
#include <math.h>

// Shapes: B=4,N=128,T=128 -> NTOK=65536 tokens, DIM=256, H=8, hd=32.
#define NTOK 65536
#define DIM  256
#define NCAT 768

// ---------------- device scratch (no allocations allowed) -------------------
__device__ __half g_a_hi[NTOK * DIM];
__device__ __half g_a_lo[NTOK * DIM];
__device__ __half g_w_h [NCAT * DIM];    // [n][k] transposed cat(Wq,Wk,Wv), fp16
__device__ __half g_wp_h[DIM * DIM];     // [n][k] transposed Wp, fp16
__device__ float  g_c[(size_t)NTOK * NCAT];     // q|k|v per token (fp32)
__device__ __half g_x_hi[NTOK * DIM];
__device__ __half g_x_lo[NTOK * DIM];

// ---------------- helpers ---------------------------------------------------
__device__ __forceinline__ void ldsm4(unsigned* r, unsigned addr) {
    asm volatile("ldmatrix.sync.aligned.m8n8.x4.shared.b16 {%0,%1,%2,%3}, [%4];"
                 : "=r"(r[0]), "=r"(r[1]), "=r"(r[2]), "=r"(r[3]) : "r"(addr));
}
__device__ __forceinline__ void mma4(float* c, const unsigned* a, unsigned b0, unsigned b1) {
    asm volatile(
        "mma.sync.aligned.m16n8k16.row.col.f32.f16.f16.f32 "
        "{%0,%1,%2,%3}, {%4,%5,%6,%7}, {%8,%9}, {%0,%1,%2,%3};\n"
        : "+f"(c[0]), "+f"(c[1]), "+f"(c[2]), "+f"(c[3])
        : "r"(a[0]), "r"(a[1]), "r"(a[2]), "r"(a[3]), "r"(b0), "r"(b1));
}
__device__ __forceinline__ uint32_t smem_u32(const void* p) {
    uint32_t a;
    asm("{ .reg .u64 t; cvta.to.shared.u64 t, %1; cvt.u32.u64 %0, t; }" : "=r"(a) : "l"(p));
    return a;
}
#define CP_ASYNC16(dst, src) \
    asm volatile("cp.async.cg.shared.global [%0], [%1], 16;" :: "r"(dst), "l"(src))
#define CP_COMMIT() asm volatile("cp.async.commit_group;" ::: "memory")
#define CP_WAIT1()  asm volatile("cp.async.wait_group 1;" ::: "memory")
#define CP_WAIT0()  asm volatile("cp.async.wait_group 0;" ::: "memory")

// ---------------- merged pre-pass -------------------------------------------
// blocks [0, 16384): input split into fp16 hi/lo (one float4 per thread)
// blocks [16384, 16384+256): weight transpose + fp16 convert (hi only).
#define SPLIT_BLOCKS 16384

__global__ __launch_bounds__(256)
void prepass_kernel(const float* __restrict__ v,
                    const float* __restrict__ Wq,
                    const float* __restrict__ Wk,
                    const float* __restrict__ Wv,
                    const float* __restrict__ Wp)
{
    __shared__ float tile[32][33];
    const int b   = blockIdx.x;
    const int tid = threadIdx.x;

    if (b < SPLIT_BLOCKS) {
        const int i = b * 256 + tid;
        const float4 x = reinterpret_cast<const float4*>(v)[i];
        __half2 h0 = __floats2half2_rn(x.x, x.y);
        __half2 h1 = __floats2half2_rn(x.z, x.w);
        __half2 l0 = __floats2half2_rn(x.x - __half2float(__low2half(h0)),
                                       x.y - __half2float(__high2half(h0)));
        __half2 l1 = __floats2half2_rn(x.z - __half2float(__low2half(h1)),
                                       x.w - __half2float(__high2half(h1)));
        reinterpret_cast<__half2*>(g_a_hi)[i * 2 + 0] = h0;
        reinterpret_cast<__half2*>(g_a_hi)[i * 2 + 1] = h1;
        reinterpret_cast<__half2*>(g_a_lo)[i * 2 + 0] = l0;
        reinterpret_cast<__half2*>(g_a_lo)[i * 2 + 1] = l1;
        return;
    }

    const int wb    = b - SPLIT_BLOCKS;   // 0..255
    const int which = wb >> 6;            // 0..3
    const int t     = wb & 63;
    const int bx = t & 7, by = t >> 3;
    const int tx = tid & 31, ty = tid >> 5;   // 32 x 8

    const float* W = (which == 0) ? Wq : (which == 1) ? Wk : (which == 2) ? Wv : Wp;
#pragma unroll
    for (int j = 0; j < 32; j += 8)
        tile[ty + j][tx] = W[(by * 32 + ty + j) * DIM + bx * 32 + tx];
    __syncthreads();
    __half* oh = (which < 3) ? (g_w_h + which * DIM * DIM) : g_wp_h;
#pragma unroll
    for (int j = 0; j < 32; j += 8) {
        const float val = tile[tx][ty + j];
        const int n = bx * 32 + ty + j;
        const int k = by * 32 + tx;
        oh[n * DIM + k] = __float2half_rn(val);
    }
}

// ---------------- HMMA GEMM, 3-stage cp.async pipeline, 2 CTAs/SM -----------
// Block tile 128(M) x 128(N), 512 threads = 16 warps as 4M x 4N, warp 32x32.
// K in 8 chunks of 32, TRIPLE-buffered, ONE __syncthreads per chunk.
// 2-pass fp16 split (A split, B single-plane): D = Ah*Bh + Al*Bh.
#define ROWP   80
#define PLANE  (128 * ROWP)          // 10240
#define STAGE  (3 * PLANE)           // 30720 (Ahi, Alo, Bh)
#define SMEM_GEMM (3 * STAGE)        // 92160 -> 2 CTAs/SM (184320 <= 228KB)

template<int ONC, bool IS_PROJ>
__global__ __launch_bounds__(512, 2)
void gemm_kernel(const __half* __restrict__ Ahi,
                 const __half* __restrict__ Alo,
                 const __half* __restrict__ Bh,
                 const float* __restrict__ bias,
                 float* __restrict__ outF)
{
    extern __shared__ __align__(128) char smem[];
    const uint32_t sbase = smem_u32(smem);

    const int tid  = threadIdx.x;
    const int warp = tid >> 5;
    const int lane = tid & 31;
    const int lane15 = lane & 15;
    const int laneHi = lane >> 4;
    const int gr = lane >> 2;
    const int qc = lane & 3;
    const int warpM = (warp >> 2) * 32;
    const int warpN = (warp & 3) * 32;
    const int colBase = blockIdx.x * 128;   // N fastest -> A-tile L2 reuse
    const int rowBase = blockIdx.y * 128;

    const int srow = tid >> 2;
    const int sseg = tid & 3;
    const uint32_t soff = srow * ROWP + sseg * 16;
    const size_t gaOff = (size_t)(rowBase + srow) * DIM + sseg * 8;
    const size_t gbOff = (size_t)(colBase + srow) * DIM + sseg * 8;

    auto issue_stage = [&](int c) {
        const uint32_t sb = sbase + (c % 3) * STAGE + soff;
        const int k0 = c * 32;
        CP_ASYNC16(sb            , Ahi + gaOff + k0);
        CP_ASYNC16(sb + PLANE    , Alo + gaOff + k0);
        CP_ASYNC16(sb + 2 * PLANE, Bh  + gbOff + k0);
        CP_COMMIT();
    };

    float acc[2][4][4];
#pragma unroll
    for (int mt = 0; mt < 2; mt++)
#pragma unroll
        for (int nt = 0; nt < 4; nt++)
#pragma unroll
            for (int i = 0; i < 4; i++) acc[mt][nt][i] = 0.f;

    const uint32_t aBase0 = sbase + (warpM + lane15) * ROWP + laneHi * 16;
    const uint32_t bBase0 = sbase + 2 * PLANE + (warpN + lane15) * ROWP + laneHi * 16;

    issue_stage(0);
    issue_stage(1);

#pragma unroll
    for (int c = 0; c < 8; c++) {
        // Pending groups at this point: c, c+1 (c+2 not yet issued) -> wait1
        // guarantees chunk c landed; at c==7 group 7 is the only/newest one.
        if (c == 7) { CP_WAIT0(); } else { CP_WAIT1(); }
        __syncthreads();
        // All warps finished computing chunk c-1 -> buffer (c-1)%3 == (c+2)%3
        // is free; refill it while we compute chunk c.
        if (c + 2 < 8) issue_stage(c + 2);

        const uint32_t aB = aBase0 + (c % 3) * STAGE;
        const uint32_t bB = bBase0 + (c % 3) * STAGE;
#pragma unroll
        for (int ks = 0; ks < 2; ks++) {
            unsigned ah[2][4], al[2][4], bh[2][4];
#pragma unroll
            for (int mt = 0; mt < 2; mt++) {
                ldsm4(ah[mt], aB + mt * (16 * ROWP) + ks * 32);
                ldsm4(al[mt], aB + mt * (16 * ROWP) + ks * 32 + PLANE);
            }
#pragma unroll
            for (int nb = 0; nb < 2; nb++)
                ldsm4(bh[nb], bB + nb * (16 * ROWP) + ks * 32);
#pragma unroll
            for (int mt = 0; mt < 2; mt++)
#pragma unroll
                for (int nb = 0; nb < 2; nb++) {
                    mma4(acc[mt][2 * nb + 0], ah[mt], bh[nb][0], bh[nb][2]);
                    mma4(acc[mt][2 * nb + 1], ah[mt], bh[nb][1], bh[nb][3]);
                    mma4(acc[mt][2 * nb + 0], al[mt], bh[nb][0], bh[nb][2]);
                    mma4(acc[mt][2 * nb + 1], al[mt], bh[nb][1], bh[nb][3]);
                }
        }
    }

    // ---- epilogue
#pragma unroll
    for (int mt = 0; mt < 2; mt++)
#pragma unroll
        for (int nb = 0; nb < 2; nb++)
#pragma unroll
            for (int j = 0; j < 2; j++) {
                const float* cc = acc[mt][2 * nb + j];
                const int r   = rowBase + warpM + mt * 16 + gr;
                const int col = colBase + warpN + nb * 16 + j * 8 + qc * 2;
                if (IS_PROJ) {
                    const float b0 = bias[col], b1 = bias[col + 1];
                    *reinterpret_cast<float2*>(&outF[(size_t)(r    ) * ONC + col]) =
                        make_float2(cc[0] + b0, cc[1] + b1);
                    *reinterpret_cast<float2*>(&outF[(size_t)(r + 8) * ONC + col]) =
                        make_float2(cc[2] + b0, cc[3] + b1);
                } else {
                    *reinterpret_cast<float2*>(&g_c[(size_t)(r    ) * ONC + col]) =
                        make_float2(cc[0], cc[1]);
                    *reinterpret_cast<float2*>(&g_c[(size_t)(r + 8) * ONC + col]) =
                        make_float2(cc[2], cc[3]);
                }
            }
}

// ---------------- per-token head-axis attention -----------------------------
__global__ __launch_bounds__(256)
void attn_kernel()
{
    const int warp = threadIdx.x >> 5;
    const int lane = threadIdx.x & 31;
    const int token = blockIdx.x * 8 + warp;
    const size_t cb = (size_t)token * NCAT;

    float qr[8], kr[8], vr[8];
#pragma unroll
    for (int hh = 0; hh < 8; hh++) {
        const int d = hh * 32 + lane;
        qr[hh] = g_c[cb +       d];
        kr[hh] = g_c[cb + 256 + d];
        vr[hh] = g_c[cb + 512 + d];
    }

    const float scale = 0.17677669529663687f;   // 32^-0.5

#pragma unroll
    for (int hh = 0; hh < 8; hh++) {
        float m = -3.0e38f, l = 0.f, acc = 0.f;
#pragma unroll
        for (int g = 0; g < 8; g++) {
            float s = qr[hh] * kr[g];
#pragma unroll
            for (int o = 16; o > 0; o >>= 1)
                s += __shfl_xor_sync(0xffffffffu, s, o);
            s *= scale;
            const float mn   = fmaxf(m, s);
            const float corr = __expf(m - mn);
            const float e    = __expf(s - mn);
            acc = acc * corr + e * vr[g];
            l   = l   * corr + e;
            m   = mn;
        }
        const float val = acc / l;
        const int d = hh * 32 + lane;
        const __half hb = __float2half_rn(val);
        g_x_hi[(size_t)token * DIM + d] = hb;
        g_x_lo[(size_t)token * DIM + d] = __float2half_rn(val - __half2float(hb));
    }
}

// ---------------------------------------------------------------------------
extern "C" void kernel_launch(void* const* d_in, const int* in_sizes, int n_in,
                              void* d_out, int out_size)
{
    const float* v  = (const float*)d_in[0];
    const float* Wq = (const float*)d_in[1];
    const float* Wk = (const float*)d_in[2];
    const float* Wv = (const float*)d_in[3];
    const float* Wp = (const float*)d_in[4];
    const float* bp = (const float*)d_in[5];
    float* out = (float*)d_out;

    void *pAhi, *pAlo, *pWh, *pPh, *pXhi, *pXlo;
    cudaGetSymbolAddress(&pAhi, g_a_hi);
    cudaGetSymbolAddress(&pAlo, g_a_lo);
    cudaGetSymbolAddress(&pWh,  g_w_h);
    cudaGetSymbolAddress(&pPh,  g_wp_h);
    cudaGetSymbolAddress(&pXhi, g_x_hi);
    cudaGetSymbolAddress(&pXlo, g_x_lo);

    cudaFuncSetAttribute(gemm_kernel<NCAT, false>,
                         cudaFuncAttributeMaxDynamicSharedMemorySize, SMEM_GEMM);
    cudaFuncSetAttribute(gemm_kernel<DIM, true>,
                         cudaFuncAttributeMaxDynamicSharedMemorySize, SMEM_GEMM);

    prepass_kernel<<<SPLIT_BLOCKS + 256, 256>>>(v, Wq, Wk, Wv, Wp);

    dim3 qkv_grid(NCAT / 128, NTOK / 128);   // (6, 512), N fastest
    gemm_kernel<NCAT, false><<<qkv_grid, 512, SMEM_GEMM>>>(
        (const __half*)pAhi, (const __half*)pAlo,
        (const __half*)pWh, nullptr, nullptr);

    attn_kernel<<<NTOK / 8, 256>>>();

    dim3 proj_grid(DIM / 128, NTOK / 128);   // (2, 512)
    gemm_kernel<DIM, true><<<proj_grid, 512, SMEM_GEMM>>>(
        (const __half*)pXhi, (const __half*)pXlo,
        (const __half*)pPh, bp, out);
}

// round 11
// speedup vs baseline: 2.0749x; 1.0274x over previous
#include <cuda_runtime.h>
#include <cuda_fp16.h>
#include <cstdint>
#include <math.h>

// Shapes: B=4,N=128,T=128 -> NTOK=65536 tokens, DIM=256, H=8, hd=32.
#define NTOK 65536
#define DIM  256
#define NCAT 768

// ---------------- device scratch (no allocations allowed) -------------------
__device__ __half g_a_hi[NTOK * DIM];
__device__ __half g_a_lo[NTOK * DIM];
__device__ __half g_w_h [NCAT * DIM];    // [n][k] transposed cat(Wq,Wk,Wv), fp16
__device__ __half g_wp_h[DIM * DIM];     // [n][k] transposed Wp, fp16
__device__ float  g_c[(size_t)NTOK * NCAT];     // q|k|v per token (fp32)
__device__ __half g_x_hi[NTOK * DIM];
__device__ __half g_x_lo[NTOK * DIM];

// ---------------- helpers ---------------------------------------------------
__device__ __forceinline__ void ldsm4(unsigned* r, unsigned addr) {
    asm volatile("ldmatrix.sync.aligned.m8n8.x4.shared.b16 {%0,%1,%2,%3}, [%4];"
                 : "=r"(r[0]), "=r"(r[1]), "=r"(r[2]), "=r"(r[3]) : "r"(addr));
}
__device__ __forceinline__ void mma4(float* c, const unsigned* a, unsigned b0, unsigned b1) {
    asm volatile(
        "mma.sync.aligned.m16n8k16.row.col.f32.f16.f16.f32 "
        "{%0,%1,%2,%3}, {%4,%5,%6,%7}, {%8,%9}, {%0,%1,%2,%3};\n"
        : "+f"(c[0]), "+f"(c[1]), "+f"(c[2]), "+f"(c[3])
        : "r"(a[0]), "r"(a[1]), "r"(a[2]), "r"(a[3]), "r"(b0), "r"(b1));
}
__device__ __forceinline__ uint32_t smem_u32(const void* p) {
    uint32_t a;
    asm("{ .reg .u64 t; cvta.to.shared.u64 t, %1; cvt.u32.u64 %0, t; }" : "=r"(a) : "l"(p));
    return a;
}
#define CP_ASYNC16(dst, src) \
    asm volatile("cp.async.cg.shared.global [%0], [%1], 16;" :: "r"(dst), "l"(src))
#define CP_COMMIT() asm volatile("cp.async.commit_group;" ::: "memory")
#define CP_WAIT1()  asm volatile("cp.async.wait_group 1;" ::: "memory")
#define CP_WAIT0()  asm volatile("cp.async.wait_group 0;" ::: "memory")

// ---------------- merged pre-pass -------------------------------------------
// blocks [0, 16384): input split into fp16 hi/lo (one float4 per thread)
// blocks [16384, 16384+256): weight transpose + fp16 convert (hi only).
#define SPLIT_BLOCKS 16384

__global__ __launch_bounds__(256)
void prepass_kernel(const float* __restrict__ v,
                    const float* __restrict__ Wq,
                    const float* __restrict__ Wk,
                    const float* __restrict__ Wv,
                    const float* __restrict__ Wp)
{
    __shared__ float tile[32][33];
    const int b   = blockIdx.x;
    const int tid = threadIdx.x;

    if (b < SPLIT_BLOCKS) {
        const int i = b * 256 + tid;
        const float4 x = reinterpret_cast<const float4*>(v)[i];
        __half2 h0 = __floats2half2_rn(x.x, x.y);
        __half2 h1 = __floats2half2_rn(x.z, x.w);
        __half2 l0 = __floats2half2_rn(x.x - __half2float(__low2half(h0)),
                                       x.y - __half2float(__high2half(h0)));
        __half2 l1 = __floats2half2_rn(x.z - __half2float(__low2half(h1)),
                                       x.w - __half2float(__high2half(h1)));
        reinterpret_cast<__half2*>(g_a_hi)[i * 2 + 0] = h0;
        reinterpret_cast<__half2*>(g_a_hi)[i * 2 + 1] = h1;
        reinterpret_cast<__half2*>(g_a_lo)[i * 2 + 0] = l0;
        reinterpret_cast<__half2*>(g_a_lo)[i * 2 + 1] = l1;
        return;
    }

    const int wb    = b - SPLIT_BLOCKS;   // 0..255
    const int which = wb >> 6;            // 0..3
    const int t     = wb & 63;
    const int bx = t & 7, by = t >> 3;
    const int tx = tid & 31, ty = tid >> 5;   // 32 x 8

    const float* W = (which == 0) ? Wq : (which == 1) ? Wk : (which == 2) ? Wv : Wp;
#pragma unroll
    for (int j = 0; j < 32; j += 8)
        tile[ty + j][tx] = W[(by * 32 + ty + j) * DIM + bx * 32 + tx];
    __syncthreads();
    __half* oh = (which < 3) ? (g_w_h + which * DIM * DIM) : g_wp_h;
#pragma unroll
    for (int j = 0; j < 32; j += 8) {
        const float val = tile[tx][ty + j];
        const int n = bx * 32 + ty + j;
        const int k = by * 32 + tx;
        oh[n * DIM + k] = __float2half_rn(val);
    }
}

// ---------------- HMMA GEMM, 3-stage cp.async, warp tile 32x64 --------------
// Block tile 128(M) x 128(N), 256 threads = 8 warps as 4M x 2N, warp 32x64.
// K in 8 chunks of 32, triple-buffered, one __syncthreads per chunk.
// 2-pass fp16 split (A split, B single-plane): D = Ah*Bh + Al*Bh.
// LDSM traffic per CTA-chunk: 8 warps * 8KB = 64KB (vs 96KB at 32x32 tiling).
#define ROWP   80
#define PLANE  (128 * ROWP)          // 10240
#define STAGE  (3 * PLANE)           // 30720 (Ahi, Alo, Bh)
#define SMEM_GEMM (3 * STAGE)        // 92160 -> 2 CTAs/SM

template<int ONC, bool IS_PROJ>
__global__ __launch_bounds__(256, 2)
void gemm_kernel(const __half* __restrict__ Ahi,
                 const __half* __restrict__ Alo,
                 const __half* __restrict__ Bh,
                 const float* __restrict__ bias,
                 float* __restrict__ outF)
{
    extern __shared__ __align__(128) char smem[];
    const uint32_t sbase = smem_u32(smem);

    const int tid  = threadIdx.x;
    const int warp = tid >> 5;
    const int lane = tid & 31;
    const int lane15 = lane & 15;
    const int laneHi = lane >> 4;
    const int gr = lane >> 2;
    const int qc = lane & 3;
    const int warpM = (warp >> 1) * 32;     // 0,32,64,96
    const int warpN = (warp & 1) * 64;      // 0,64
    const int colBase = blockIdx.x * 128;   // N fastest -> A-tile L2 reuse
    const int rowBase = blockIdx.y * 128;

    // staging: 256 threads; each thread covers rows (r, r+64), one 16B seg.
    const int srow = tid >> 2;              // 0..63
    const int sg   = tid & 3;               // 0..3
    const uint32_t off0 = srow * ROWP + sg * 16;
    const uint32_t off1 = off0 + 64 * ROWP;
    const size_t ga0 = (size_t)(rowBase + srow) * DIM + sg * 8;
    const size_t ga1 = ga0 + (size_t)64 * DIM;
    const size_t gb0 = (size_t)(colBase + srow) * DIM + sg * 8;
    const size_t gb1 = gb0 + (size_t)64 * DIM;

    auto issue_stage = [&](int c) {
        const uint32_t sb = sbase + (c % 3) * STAGE;
        const int k0 = c * 32;
        CP_ASYNC16(sb + off0            , Ahi + ga0 + k0);
        CP_ASYNC16(sb + off1            , Ahi + ga1 + k0);
        CP_ASYNC16(sb + off0 + PLANE    , Alo + ga0 + k0);
        CP_ASYNC16(sb + off1 + PLANE    , Alo + ga1 + k0);
        CP_ASYNC16(sb + off0 + 2 * PLANE, Bh  + gb0 + k0);
        CP_ASYNC16(sb + off1 + 2 * PLANE, Bh  + gb1 + k0);
        CP_COMMIT();
    };

    float acc[2][8][4];
#pragma unroll
    for (int mt = 0; mt < 2; mt++)
#pragma unroll
        for (int nt = 0; nt < 8; nt++)
#pragma unroll
            for (int i = 0; i < 4; i++) acc[mt][nt][i] = 0.f;

    const uint32_t aBase0 = sbase + (warpM + lane15) * ROWP + laneHi * 16;
    const uint32_t bBase0 = sbase + 2 * PLANE + (warpN + lane15) * ROWP + laneHi * 16;

    issue_stage(0);
    issue_stage(1);

#pragma unroll
    for (int c = 0; c < 8; c++) {
        if (c == 7) { CP_WAIT0(); } else { CP_WAIT1(); }
        __syncthreads();
        if (c + 2 < 8) issue_stage(c + 2);   // buffer (c-1)%3 == (c+2)%3 is free

        const uint32_t aB = aBase0 + (c % 3) * STAGE;
        const uint32_t bB = bBase0 + (c % 3) * STAGE;
#pragma unroll
        for (int ks = 0; ks < 2; ks++) {
            unsigned ah[2][4], al[2][4], bh[4][4];
#pragma unroll
            for (int mt = 0; mt < 2; mt++) {
                ldsm4(ah[mt], aB + mt * (16 * ROWP) + ks * 32);
                ldsm4(al[mt], aB + mt * (16 * ROWP) + ks * 32 + PLANE);
            }
#pragma unroll
            for (int nb = 0; nb < 4; nb++)
                ldsm4(bh[nb], bB + nb * (16 * ROWP) + ks * 32);
#pragma unroll
            for (int mt = 0; mt < 2; mt++)
#pragma unroll
                for (int nb = 0; nb < 4; nb++) {
                    mma4(acc[mt][2 * nb + 0], ah[mt], bh[nb][0], bh[nb][2]);
                    mma4(acc[mt][2 * nb + 1], ah[mt], bh[nb][1], bh[nb][3]);
                    mma4(acc[mt][2 * nb + 0], al[mt], bh[nb][0], bh[nb][2]);
                    mma4(acc[mt][2 * nb + 1], al[mt], bh[nb][1], bh[nb][3]);
                }
        }
    }

    // ---- epilogue
#pragma unroll
    for (int mt = 0; mt < 2; mt++)
#pragma unroll
        for (int t = 0; t < 8; t++) {
            const float* cc = acc[mt][t];
            const int r   = rowBase + warpM + mt * 16 + gr;
            const int col = colBase + warpN + t * 8 + qc * 2;
            if (IS_PROJ) {
                const float b0 = bias[col], b1 = bias[col + 1];
                *reinterpret_cast<float2*>(&outF[(size_t)(r    ) * ONC + col]) =
                    make_float2(cc[0] + b0, cc[1] + b1);
                *reinterpret_cast<float2*>(&outF[(size_t)(r + 8) * ONC + col]) =
                    make_float2(cc[2] + b0, cc[3] + b1);
            } else {
                *reinterpret_cast<float2*>(&g_c[(size_t)(r    ) * ONC + col]) =
                    make_float2(cc[0], cc[1]);
                *reinterpret_cast<float2*>(&g_c[(size_t)(r + 8) * ONC + col]) =
                    make_float2(cc[2], cc[3]);
            }
        }
}

// ---------------- per-token head-axis attention -----------------------------
__global__ __launch_bounds__(256)
void attn_kernel()
{
    const int warp = threadIdx.x >> 5;
    const int lane = threadIdx.x & 31;
    const int token = blockIdx.x * 8 + warp;
    const size_t cb = (size_t)token * NCAT;

    float qr[8], kr[8], vr[8];
#pragma unroll
    for (int hh = 0; hh < 8; hh++) {
        const int d = hh * 32 + lane;
        qr[hh] = g_c[cb +       d];
        kr[hh] = g_c[cb + 256 + d];
        vr[hh] = g_c[cb + 512 + d];
    }

    const float scale = 0.17677669529663687f;   // 32^-0.5

#pragma unroll
    for (int hh = 0; hh < 8; hh++) {
        float m = -3.0e38f, l = 0.f, acc = 0.f;
#pragma unroll
        for (int g = 0; g < 8; g++) {
            float s = qr[hh] * kr[g];
#pragma unroll
            for (int o = 16; o > 0; o >>= 1)
                s += __shfl_xor_sync(0xffffffffu, s, o);
            s *= scale;
            const float mn   = fmaxf(m, s);
            const float corr = __expf(m - mn);
            const float e    = __expf(s - mn);
            acc = acc * corr + e * vr[g];
            l   = l   * corr + e;
            m   = mn;
        }
        const float val = acc / l;
        const int d = hh * 32 + lane;
        const __half hb = __float2half_rn(val);
        g_x_hi[(size_t)token * DIM + d] = hb;
        g_x_lo[(size_t)token * DIM + d] = __float2half_rn(val - __half2float(hb));
    }
}

// ---------------------------------------------------------------------------
extern "C" void kernel_launch(void* const* d_in, const int* in_sizes, int n_in,
                              void* d_out, int out_size)
{
    const float* v  = (const float*)d_in[0];
    const float* Wq = (const float*)d_in[1];
    const float* Wk = (const float*)d_in[2];
    const float* Wv = (const float*)d_in[3];
    const float* Wp = (const float*)d_in[4];
    const float* bp = (const float*)d_in[5];
    float* out = (float*)d_out;

    void *pAhi, *pAlo, *pWh, *pPh, *pXhi, *pXlo;
    cudaGetSymbolAddress(&pAhi, g_a_hi);
    cudaGetSymbolAddress(&pAlo, g_a_lo);
    cudaGetSymbolAddress(&pWh,  g_w_h);
    cudaGetSymbolAddress(&pPh,  g_wp_h);
    cudaGetSymbolAddress(&pXhi, g_x_hi);
    cudaGetSymbolAddress(&pXlo, g_x_lo);

    cudaFuncSetAttribute(gemm_kernel<NCAT, false>,
                         cudaFuncAttributeMaxDynamicSharedMemorySize, SMEM_GEMM);
    cudaFuncSetAttribute(gemm_kernel<DIM, true>,
                         cudaFuncAttributeMaxDynamicSharedMemorySize, SMEM_GEMM);

    prepass_kernel<<<SPLIT_BLOCKS + 256, 256>>>(v, Wq, Wk, Wv, Wp);

    dim3 qkv_grid(NCAT / 128, NTOK / 128);   // (6, 512), N fastest
    gemm_kernel<NCAT, false><<<qkv_grid, 256, SMEM_GEMM>>>(
        (const __half*)pAhi, (const __half*)pAlo,
        (const __half*)pWh, nullptr, nullptr);

    attn_kernel<<<NTOK / 8, 256>>>();

    dim3 proj_grid(DIM / 128, NTOK / 128);   // (2, 512)
    gemm_kernel<DIM, true><<<proj_grid, 256, SMEM_GEMM>>>(
        (const __half*)pXhi, (const __half*)pXlo,
        (const __half*)pPh, bp, out);
}

// round 12
// speedup vs baseline: 2.7888x; 1.3441x over previous
#include <cuda_runtime.h>
#include <cuda_fp16.h>
#include <cstdint>
#include <math.h>

// Shapes: B=4,N=128,T=128 -> NTOK=65536 tokens, DIM=256, H=8, hd=32.
#define NTOK 65536
#define DIM  256
#define NCAT 768

// ---------------- device scratch (no allocations allowed) -------------------
__device__ __half g_a_h[NTOK * DIM];     // input, fp16
__device__ __half g_w_h [NCAT * DIM];    // [n][k] transposed cat(Wq,Wk,Wv), fp16
__device__ __half g_wp_h[DIM * DIM];     // [n][k] transposed Wp, fp16
__device__ float  g_c[(size_t)NTOK * NCAT];     // q|k|v per token (fp32)
__device__ __half g_x_h[NTOK * DIM];     // attention output, fp16

// ---------------- helpers ---------------------------------------------------
__device__ __forceinline__ void ldsm4(unsigned* r, unsigned addr) {
    asm volatile("ldmatrix.sync.aligned.m8n8.x4.shared.b16 {%0,%1,%2,%3}, [%4];"
                 : "=r"(r[0]), "=r"(r[1]), "=r"(r[2]), "=r"(r[3]) : "r"(addr));
}
__device__ __forceinline__ void mma4(float* c, const unsigned* a, unsigned b0, unsigned b1) {
    asm volatile(
        "mma.sync.aligned.m16n8k16.row.col.f32.f16.f16.f32 "
        "{%0,%1,%2,%3}, {%4,%5,%6,%7}, {%8,%9}, {%0,%1,%2,%3};\n"
        : "+f"(c[0]), "+f"(c[1]), "+f"(c[2]), "+f"(c[3])
        : "r"(a[0]), "r"(a[1]), "r"(a[2]), "r"(a[3]), "r"(b0), "r"(b1));
}
__device__ __forceinline__ uint32_t smem_u32(const void* p) {
    uint32_t a;
    asm("{ .reg .u64 t; cvta.to.shared.u64 t, %1; cvt.u32.u64 %0, t; }" : "=r"(a) : "l"(p));
    return a;
}
#define CP_ASYNC16(dst, src) \
    asm volatile("cp.async.cg.shared.global [%0], [%1], 16;" :: "r"(dst), "l"(src))
#define CP_COMMIT() asm volatile("cp.async.commit_group;" ::: "memory")
#define CP_WAIT1()  asm volatile("cp.async.wait_group 1;" ::: "memory")
#define CP_WAIT0()  asm volatile("cp.async.wait_group 0;" ::: "memory")

// ---------------- merged pre-pass -------------------------------------------
// blocks [0, 16384): input convert to fp16 (one float4 per thread)
// blocks [16384, 16384+256): weight transpose + fp16 convert.
#define SPLIT_BLOCKS 16384

__global__ __launch_bounds__(256)
void prepass_kernel(const float* __restrict__ v,
                    const float* __restrict__ Wq,
                    const float* __restrict__ Wk,
                    const float* __restrict__ Wv,
                    const float* __restrict__ Wp)
{
    __shared__ float tile[32][33];
    const int b   = blockIdx.x;
    const int tid = threadIdx.x;

    if (b < SPLIT_BLOCKS) {
        const int i = b * 256 + tid;
        const float4 x = reinterpret_cast<const float4*>(v)[i];
        __half2 h0 = __floats2half2_rn(x.x, x.y);
        __half2 h1 = __floats2half2_rn(x.z, x.w);
        reinterpret_cast<__half2*>(g_a_h)[i * 2 + 0] = h0;
        reinterpret_cast<__half2*>(g_a_h)[i * 2 + 1] = h1;
        return;
    }

    const int wb    = b - SPLIT_BLOCKS;   // 0..255
    const int which = wb >> 6;            // 0..3
    const int t     = wb & 63;
    const int bx = t & 7, by = t >> 3;
    const int tx = tid & 31, ty = tid >> 5;   // 32 x 8

    const float* W = (which == 0) ? Wq : (which == 1) ? Wk : (which == 2) ? Wv : Wp;
#pragma unroll
    for (int j = 0; j < 32; j += 8)
        tile[ty + j][tx] = W[(by * 32 + ty + j) * DIM + bx * 32 + tx];
    __syncthreads();
    __half* oh = (which < 3) ? (g_w_h + which * DIM * DIM) : g_wp_h;
#pragma unroll
    for (int j = 0; j < 32; j += 8) {
        const float val = tile[tx][ty + j];
        const int n = bx * 32 + ty + j;
        const int k = by * 32 + tx;
        oh[n * DIM + k] = __float2half_rn(val);
    }
}

// ---------------- HMMA GEMM, single-pass fp16, 3-stage cp.async -------------
// Block tile 128(M) x 128(N), 256 threads = 8 warps as 4M x 2N, warp 32x64.
// K in 8 chunks of 32, triple-buffered, one __syncthreads per chunk.
#define ROWP   80
#define PLANE  (128 * ROWP)          // 10240
#define STAGE  (2 * PLANE)           // 20480 (A, B)
#define SMEM_GEMM (3 * STAGE)        // 61440 -> 2 CTAs/SM

template<int ONC, bool IS_PROJ>
__global__ __launch_bounds__(256, 2)
void gemm_kernel(const __half* __restrict__ Ah,
                 const __half* __restrict__ Bh,
                 const float* __restrict__ bias,
                 float* __restrict__ outF)
{
    extern __shared__ __align__(128) char smem[];
    const uint32_t sbase = smem_u32(smem);

    const int tid  = threadIdx.x;
    const int warp = tid >> 5;
    const int lane = tid & 31;
    const int lane15 = lane & 15;
    const int laneHi = lane >> 4;
    const int gr = lane >> 2;
    const int qc = lane & 3;
    const int warpM = (warp >> 1) * 32;     // 0,32,64,96
    const int warpN = (warp & 1) * 64;      // 0,64
    const int colBase = blockIdx.x * 128;   // N fastest -> A-tile L2 reuse
    const int rowBase = blockIdx.y * 128;

    // staging: 256 threads; each thread covers rows (r, r+64), one 16B seg.
    const int srow = tid >> 2;              // 0..63
    const int sg   = tid & 3;               // 0..3
    const uint32_t off0 = srow * ROWP + sg * 16;
    const uint32_t off1 = off0 + 64 * ROWP;
    const size_t ga0 = (size_t)(rowBase + srow) * DIM + sg * 8;
    const size_t ga1 = ga0 + (size_t)64 * DIM;
    const size_t gb0 = (size_t)(colBase + srow) * DIM + sg * 8;
    const size_t gb1 = gb0 + (size_t)64 * DIM;

    auto issue_stage = [&](int c) {
        const uint32_t sb = sbase + (c % 3) * STAGE;
        const int k0 = c * 32;
        CP_ASYNC16(sb + off0        , Ah + ga0 + k0);
        CP_ASYNC16(sb + off1        , Ah + ga1 + k0);
        CP_ASYNC16(sb + off0 + PLANE, Bh + gb0 + k0);
        CP_ASYNC16(sb + off1 + PLANE, Bh + gb1 + k0);
        CP_COMMIT();
    };

    float acc[2][8][4];
#pragma unroll
    for (int mt = 0; mt < 2; mt++)
#pragma unroll
        for (int nt = 0; nt < 8; nt++)
#pragma unroll
            for (int i = 0; i < 4; i++) acc[mt][nt][i] = 0.f;

    const uint32_t aBase0 = sbase + (warpM + lane15) * ROWP + laneHi * 16;
    const uint32_t bBase0 = sbase + PLANE + (warpN + lane15) * ROWP + laneHi * 16;

    issue_stage(0);
    issue_stage(1);

#pragma unroll
    for (int c = 0; c < 8; c++) {
        if (c == 7) { CP_WAIT0(); } else { CP_WAIT1(); }
        __syncthreads();
        if (c + 2 < 8) issue_stage(c + 2);   // buffer (c-1)%3 == (c+2)%3 is free

        const uint32_t aB = aBase0 + (c % 3) * STAGE;
        const uint32_t bB = bBase0 + (c % 3) * STAGE;
#pragma unroll
        for (int ks = 0; ks < 2; ks++) {
            unsigned ah[2][4], bh[4][4];
#pragma unroll
            for (int mt = 0; mt < 2; mt++)
                ldsm4(ah[mt], aB + mt * (16 * ROWP) + ks * 32);
#pragma unroll
            for (int nb = 0; nb < 4; nb++)
                ldsm4(bh[nb], bB + nb * (16 * ROWP) + ks * 32);
#pragma unroll
            for (int mt = 0; mt < 2; mt++)
#pragma unroll
                for (int nb = 0; nb < 4; nb++) {
                    mma4(acc[mt][2 * nb + 0], ah[mt], bh[nb][0], bh[nb][2]);
                    mma4(acc[mt][2 * nb + 1], ah[mt], bh[nb][1], bh[nb][3]);
                }
        }
    }

    // ---- epilogue
#pragma unroll
    for (int mt = 0; mt < 2; mt++)
#pragma unroll
        for (int t = 0; t < 8; t++) {
            const float* cc = acc[mt][t];
            const int r   = rowBase + warpM + mt * 16 + gr;
            const int col = colBase + warpN + t * 8 + qc * 2;
            if (IS_PROJ) {
                const float b0 = bias[col], b1 = bias[col + 1];
                *reinterpret_cast<float2*>(&outF[(size_t)(r    ) * ONC + col]) =
                    make_float2(cc[0] + b0, cc[1] + b1);
                *reinterpret_cast<float2*>(&outF[(size_t)(r + 8) * ONC + col]) =
                    make_float2(cc[2] + b0, cc[3] + b1);
            } else {
                *reinterpret_cast<float2*>(&g_c[(size_t)(r    ) * ONC + col]) =
                    make_float2(cc[0], cc[1]);
                *reinterpret_cast<float2*>(&g_c[(size_t)(r + 8) * ONC + col]) =
                    make_float2(cc[2], cc[3]);
            }
        }
}

// ---------------- per-token head-axis attention -----------------------------
__global__ __launch_bounds__(256)
void attn_kernel()
{
    const int warp = threadIdx.x >> 5;
    const int lane = threadIdx.x & 31;
    const int token = blockIdx.x * 8 + warp;
    const size_t cb = (size_t)token * NCAT;

    float qr[8], kr[8], vr[8];
#pragma unroll
    for (int hh = 0; hh < 8; hh++) {
        const int d = hh * 32 + lane;
        qr[hh] = g_c[cb +       d];
        kr[hh] = g_c[cb + 256 + d];
        vr[hh] = g_c[cb + 512 + d];
    }

    const float scale = 0.17677669529663687f;   // 32^-0.5

#pragma unroll
    for (int hh = 0; hh < 8; hh++) {
        float m = -3.0e38f, l = 0.f, acc = 0.f;
#pragma unroll
        for (int g = 0; g < 8; g++) {
            float s = qr[hh] * kr[g];
#pragma unroll
            for (int o = 16; o > 0; o >>= 1)
                s += __shfl_xor_sync(0xffffffffu, s, o);
            s *= scale;
            const float mn   = fmaxf(m, s);
            const float corr = __expf(m - mn);
            const float e    = __expf(s - mn);
            acc = acc * corr + e * vr[g];
            l   = l   * corr + e;
            m   = mn;
        }
        const float val = acc / l;
        const int d = hh * 32 + lane;
        g_x_h[(size_t)token * DIM + d] = __float2half_rn(val);
    }
}

// ---------------------------------------------------------------------------
extern "C" void kernel_launch(void* const* d_in, const int* in_sizes, int n_in,
                              void* d_out, int out_size)
{
    const float* v  = (const float*)d_in[0];
    const float* Wq = (const float*)d_in[1];
    const float* Wk = (const float*)d_in[2];
    const float* Wv = (const float*)d_in[3];
    const float* Wp = (const float*)d_in[4];
    const float* bp = (const float*)d_in[5];
    float* out = (float*)d_out;

    void *pAh, *pWh, *pPh, *pXh;
    cudaGetSymbolAddress(&pAh, g_a_h);
    cudaGetSymbolAddress(&pWh, g_w_h);
    cudaGetSymbolAddress(&pPh, g_wp_h);
    cudaGetSymbolAddress(&pXh, g_x_h);

    cudaFuncSetAttribute(gemm_kernel<NCAT, false>,
                         cudaFuncAttributeMaxDynamicSharedMemorySize, SMEM_GEMM);
    cudaFuncSetAttribute(gemm_kernel<DIM, true>,
                         cudaFuncAttributeMaxDynamicSharedMemorySize, SMEM_GEMM);

    prepass_kernel<<<SPLIT_BLOCKS + 256, 256>>>(v, Wq, Wk, Wv, Wp);

    dim3 qkv_grid(NCAT / 128, NTOK / 128);   // (6, 512), N fastest
    gemm_kernel<NCAT, false><<<qkv_grid, 256, SMEM_GEMM>>>(
        (const __half*)pAh, (const __half*)pWh, nullptr, nullptr);

    attn_kernel<<<NTOK / 8, 256>>>();

    dim3 proj_grid(DIM / 128, NTOK / 128);   // (2, 512)
    gemm_kernel<DIM, true><<<proj_grid, 256, SMEM_GEMM>>>(
        (const __half*)pXh, (const __half*)pPh, bp, out);
}